// round 9
// baseline (speedup 1.0000x reference)
#include <cuda_runtime.h>
#include <math.h>
#include <stdint.h>

typedef unsigned long long ull;

#define NB 128
#define HH 128
#define WW 128

// ---------------- packed fp32x2 helpers (sm_100+) ----------------
__device__ __forceinline__ ull fma2(ull a, ull b, ull c) {
    ull d;
    asm("fma.rn.f32x2 %0, %1, %2, %3;" : "=l"(d) : "l"(a), "l"(b), "l"(c));
    return d;
}
__device__ __forceinline__ ull pack2(float lo, float hi) {
    return ((ull)__float_as_uint(hi) << 32) | (ull)__float_as_uint(lo);
}
__device__ __forceinline__ float sum2(ull v) {
    return __uint_as_float((unsigned)v) + __uint_as_float((unsigned)(v >> 32));
}

// tf32 round (rna)
__device__ __forceinline__ float f2tf(float f) {
    uint32_t r;
    asm("cvt.rna.tf32.f32 %0, %1;" : "=r"(r) : "f"(f));
    return __uint_as_float(r);
}

// ---------------- scratch (static device arrays; no allocs) ----------------
__device__ float g_h[NB * 2 * HH * WW];        // 16 MB: conv1 output
__device__ float g_feat[NB * 8192];            // pooled features (f32)
__device__ float g_part1[8 * NB * 2048];       // fc1 split-K partials
__device__ float g_act1[NB * 2048];            // relu(fc1+b)
__device__ float g_part2[16 * NB * 1024];      // fc2 split-K partials

// ---------------- no-op spacers: align dcn to ncu's capture window ----------
__global__ void noop_kernel() {
    if (blockIdx.x == 0xFFFFFFFFu) g_act1[0] = 0.f;  // never taken
}

// ---------------- conv1: z=concat(x,mask), 3x3 pad1, 9->2 ch ----------------
__global__ void __launch_bounds__(256) conv1_kernel(
    const float* __restrict__ x, const float* __restrict__ mask,
    const float* __restrict__ w1, const float* __restrict__ b1)
{
    __shared__ float s[9 * 10 * 34];
    __shared__ float ws[162];
    __shared__ float bs[2];
    int n = blockIdx.z;
    int ty0 = blockIdx.y * 8, tx0 = blockIdx.x * 32;
    int tid = threadIdx.y * 32 + threadIdx.x;
    if (tid < 162) ws[tid] = w1[tid];
    if (tid < 2) bs[tid] = b1[tid];
    for (int i = tid; i < 9 * 340; i += 256) {
        int c = i / 340, rem = i % 340;
        int yy = rem / 34, xx = rem % 34;
        int gy = ty0 + yy - 1, gx = tx0 + xx - 1;
        float v = 0.f;
        if (gy >= 0 && gy < HH && gx >= 0 && gx < WW)
            v = (c < 8) ? x[((n * 8 + c) * HH + gy) * WW + gx]
                        : mask[(n * HH + gy) * WW + gx];
        s[i] = v;
    }
    __syncthreads();
    int ty = threadIdx.y, tx = threadIdx.x;
    float a0 = bs[0], a1 = bs[1];
#pragma unroll
    for (int c = 0; c < 9; c++)
#pragma unroll
        for (int ky = 0; ky < 3; ky++)
#pragma unroll
            for (int kx = 0; kx < 3; kx++) {
                float v = s[c * 340 + (ty + ky) * 34 + (tx + kx)];
                a0 += v * ws[(0 * 9 + c) * 9 + ky * 3 + kx];
                a1 += v * ws[(1 * 9 + c) * 9 + ky * 3 + kx];
            }
    int oy = ty0 + ty, ox = tx0 + tx;
    g_h[((n * 2 + 0) * HH + oy) * WW + ox] = a0;
    g_h[((n * 2 + 1) * HH + oy) * WW + ox] = a1;
}

// ---------------- fused DCN stage: one CTA per image, 512 threads -------------
// Offset conv computed lazily per tap k (3 dots over t2[9]) to keep the peak
// register live-set small (no om[27] array) — spill-proof at 512 thr/128-reg cap.
__global__ void __launch_bounds__(512) dcn_kernel(
    const float* __restrict__ w_off, const float* __restrict__ w_dcn,
    const float* __restrict__ b_dcn, const float* __restrict__ w2,
    const float* __restrict__ b2)
{
    extern __shared__ float sm[];
    float* hs  = sm;            // 32768 floats (2 x 128 x 128)
    float* wof = sm + 32768;    // 486
    float* wd  = wof + 486;     // 36
    float* w2s = wd + 36;       // 4
    float* bds = w2s + 4;       // 2
    float* b2s = bds + 2;       // 2
    int n = blockIdx.x;
    int tid = threadIdx.x;  // 512

    const float4* src = (const float4*)(g_h + n * 32768);
    float4* dst = (float4*)hs;
    for (int i = tid; i < 8192; i += 512) dst[i] = src[i];
    if (tid < 486) wof[tid] = w_off[tid];
    if (tid < 36) wd[tid] = w_dcn[tid];
    if (tid < 4) w2s[tid] = w2[tid];
    if (tid < 2) { bds[tid] = b_dcn[tid]; b2s[tid] = b2[tid]; }
    __syncthreads();

    const ull* wof2 = (const ull*)wof;

#pragma unroll 1
    for (int idx = tid; idx < 4096; idx += 512) {
        int py = idx >> 6, px = idx & 63;
        float m0 = -1e30f, m1 = -1e30f;
#pragma unroll 1
        for (int sub = 0; sub < 4; sub++) {
            int y = py * 2 + (sub >> 1);
            int x = px * 2 + (sub & 1);

            // gather the 18 dilated taps of h around (y,x)
            float t[18];
            if (y >= 3 && y < HH - 3 && x >= 3 && x < WW - 3) {
                const float* p = hs + y * 128 + x;
#pragma unroll
                for (int c = 0; c < 2; c++)
#pragma unroll
                    for (int j = 0; j < 9; j++)
                        t[c * 9 + j] = p[c * 16384 + (j / 3 - 1) * 384 + (j % 3 - 1) * 3];
            } else {
#pragma unroll
                for (int c = 0; c < 2; c++)
#pragma unroll
                    for (int j = 0; j < 9; j++) {
                        int yy = y + (j / 3 - 1) * 3;
                        int xx = x + (j % 3 - 1) * 3;
                        float v = 0.f;
                        if (yy >= 0 && yy < HH && xx >= 0 && xx < WW)
                            v = hs[c * 16384 + yy * 128 + xx];
                        t[c * 9 + j] = v;
                    }
            }
            ull t2[9];
#pragma unroll
            for (int p = 0; p < 9; p++) t2[p] = pack2(t[2 * p], t[2 * p + 1]);

            float a0 = bds[0], a1 = bds[1];
#pragma unroll
            for (int k = 0; k < 9; k++) {
                // lazy offset-conv: channels 2k (dy), 2k+1 (dx), 18+k (mask)
                const ull* wy = wof2 + (2 * k) * 9;
                const ull* wx = wof2 + (2 * k + 1) * 9;
                const ull* wM = wof2 + (18 + k) * 9;
                ull accY = 0ull, accX = 0ull, accM = 0ull;
#pragma unroll
                for (int p = 0; p < 9; p++) {
                    accY = fma2(t2[p], wy[p], accY);
                    accX = fma2(t2[p], wx[p], accX);
                    accM = fma2(t2[p], wM[p], accM);
                }
                float fy = sum2(accY) + (float)(y + (k / 3 - 1) * 3);
                float fx = sum2(accX) + (float)(x + (k % 3 - 1) * 3);
                float mmk = 1.f / (1.f + __expf(-sum2(accM)));

                float y0f = floorf(fy), x0f = floorf(fx);
                int iy0 = (int)y0f, ix0 = (int)x0f;
                float ly = fy - y0f, lx = fx - x0f;
                float c00 = (1.f - ly) * (1.f - lx), c01 = (1.f - ly) * lx;
                float c10 = ly * (1.f - lx),         c11 = ly * lx;
                bool vy0 = (iy0 >= 0) && (iy0 < HH);
                bool vy1 = (iy0 + 1 >= 0) && (iy0 + 1 < HH);
                bool vx0 = (ix0 >= 0) && (ix0 < WW);
                bool vx1 = (ix0 + 1 >= 0) && (ix0 + 1 < WW);
                int cy0 = min(max(iy0, 0), HH - 1), cy1 = min(max(iy0 + 1, 0), HH - 1);
                int cx0 = min(max(ix0, 0), WW - 1), cx1 = min(max(ix0 + 1, 0), WW - 1);
#pragma unroll
                for (int c = 0; c < 2; c++) {
                    const float* hb = hs + c * 16384;
                    float v00 = (vy0 && vx0) ? hb[cy0 * 128 + cx0] : 0.f;
                    float v01 = (vy0 && vx1) ? hb[cy0 * 128 + cx1] : 0.f;
                    float v10 = (vy1 && vx0) ? hb[cy1 * 128 + cx0] : 0.f;
                    float v11 = (vy1 && vx1) ? hb[cy1 * 128 + cx1] : 0.f;
                    float sc = (v00 * c00 + v01 * c01 + v10 * c10 + v11 * c11) * mmk;
                    a0 += sc * wd[0 * 18 + c * 9 + k];
                    a1 += sc * wd[1 * 18 + c * 9 + k];
                }
            }
            float o0 = fmaxf(a0 * w2s[0] + a1 * w2s[1] + b2s[0], 0.f);
            float o1 = fmaxf(a0 * w2s[2] + a1 * w2s[3] + b2s[1], 0.f);
            m0 = fmaxf(m0, o0);
            m1 = fmaxf(m1, o1);
        }
        g_feat[n * 8192 + idx]        = m0;   // channel 0
        g_feat[n * 8192 + 4096 + idx] = m1;   // channel 1
    }
}

// ---------------- tf32 tensor-core GEMM: C_part = A(128 x LDK) @ B^T ----------
__device__ __forceinline__ void mma_tf32(float4& c, const uint32_t* a,
                                         uint32_t b0, uint32_t b1) {
    asm volatile(
        "mma.sync.aligned.m16n8k8.row.col.f32.tf32.tf32.f32 "
        "{%0,%1,%2,%3}, {%4,%5,%6,%7}, {%8,%9}, {%0,%1,%2,%3};\n"
        : "+f"(c.x), "+f"(c.y), "+f"(c.z), "+f"(c.w)
        : "r"(a[0]), "r"(a[1]), "r"(a[2]), "r"(a[3]), "r"(b0), "r"(b1));
}

template <int NTOT, int KCH, int LDK>
__global__ void __launch_bounds__(256) gemm_tf32_kernel(
    const float* __restrict__ A, const float* __restrict__ B,
    float* __restrict__ part)
{
    __shared__ float As[128 * 36];
    __shared__ float Bs[128 * 36];
    int ntile = blockIdx.x, kz = blockIdx.y;
    int tid = threadIdx.x;
    int warp = tid >> 5, lane = tid & 31;
    int g = lane >> 2, t = lane & 3;
    int wm = warp >> 1, wn = warp & 1;

    float4 acc[2][8];
#pragma unroll
    for (int i = 0; i < 2; i++)
#pragma unroll
        for (int j = 0; j < 8; j++) acc[i][j] = make_float4(0.f, 0.f, 0.f, 0.f);

    int k0base = kz * KCH;
    for (int s = 0; s < KCH; s += 32) {
        int k0 = k0base + s;
#pragma unroll
        for (int i = 0; i < 4; i++) {
            int lin = tid + i * 256;           // 0..1023
            int row = lin >> 3, cw = (lin & 7) * 4;
            float4 va = *(const float4*)&A[row * LDK + k0 + cw];
            float4 vb = *(const float4*)&B[(ntile * 128 + row) * LDK + k0 + cw];
            float4 ta = make_float4(f2tf(va.x), f2tf(va.y), f2tf(va.z), f2tf(va.w));
            float4 tb = make_float4(f2tf(vb.x), f2tf(vb.y), f2tf(vb.z), f2tf(vb.w));
            *(float4*)&As[row * 36 + cw] = ta;
            *(float4*)&Bs[row * 36 + cw] = tb;
        }
        __syncthreads();
#pragma unroll
        for (int kk = 0; kk < 32; kk += 8) {
            uint32_t a[2][4];
#pragma unroll
            for (int im = 0; im < 2; im++) {
                int r = wm * 32 + im * 16 + g;
                a[im][0] = __float_as_uint(As[r * 36 + kk + t]);
                a[im][1] = __float_as_uint(As[(r + 8) * 36 + kk + t]);
                a[im][2] = __float_as_uint(As[r * 36 + kk + t + 4]);
                a[im][3] = __float_as_uint(As[(r + 8) * 36 + kk + t + 4]);
            }
#pragma unroll
            for (int jn = 0; jn < 8; jn++) {
                int rb = wn * 64 + jn * 8 + g;
                uint32_t b0 = __float_as_uint(Bs[rb * 36 + kk + t]);
                uint32_t b1 = __float_as_uint(Bs[rb * 36 + kk + t + 4]);
                mma_tf32(acc[0][jn], a[0], b0, b1);
                mma_tf32(acc[1][jn], a[1], b0, b1);
            }
        }
        __syncthreads();
    }

    float* P = part + (size_t)kz * 128 * NTOT;
#pragma unroll
    for (int im = 0; im < 2; im++)
#pragma unroll
        for (int jn = 0; jn < 8; jn++) {
            int r0 = wm * 32 + im * 16 + g;
            int col = ntile * 128 + wn * 64 + jn * 8 + 2 * t;
            float4 c = acc[im][jn];
            *(float2*)&P[r0 * NTOT + col]       = make_float2(c.x, c.y);
            *(float2*)&P[(r0 + 8) * NTOT + col] = make_float2(c.z, c.w);
        }
}

// ---------------- act1: reduce fc1 partials + bias + relu ----------------
__global__ void __launch_bounds__(256) act1_kernel(const float* __restrict__ fc1_b) {
    int i = blockIdx.x * 256 + threadIdx.x;   // 0 .. 128*2048-1
    float v = fc1_b[i & 2047];
#pragma unroll
    for (int kz = 0; kz < 8; kz++) v += g_part1[kz * (NB * 2048) + i];
    g_act1[i] = fmaxf(v, 0.f);
}

// ---------------- final: reduce fc2 partials + bias + relu, dot io_w, sigmoid --
__global__ void __launch_bounds__(256) io_kernel(
    const float* __restrict__ fc2_b, const float* __restrict__ io_w,
    const float* __restrict__ io_b, float* __restrict__ out)
{
    int n = blockIdx.x;
    int tid = threadIdx.x;
    float s = 0.f;
    for (int k = tid; k < 1024; k += 256) {
        float v = fc2_b[k];
#pragma unroll
        for (int kz = 0; kz < 16; kz++)
            v += g_part2[kz * (NB * 1024) + n * 1024 + k];
        s += fmaxf(v, 0.f) * io_w[k];
    }
#pragma unroll
    for (int o = 16; o > 0; o >>= 1) s += __shfl_down_sync(0xffffffffu, s, o);
    __shared__ float red[8];
    if ((tid & 31) == 0) red[tid >> 5] = s;
    __syncthreads();
    if (tid == 0) {
        float tt = 0.f;
#pragma unroll
        for (int i = 0; i < 8; i++) tt += red[i];
        out[n] = 1.f / (1.f + __expf(-(tt + io_b[0])));
    }
}

extern "C" void kernel_launch(void* const* d_in, const int* in_sizes, int n_in,
                              void* d_out, int out_size) {
    const float* mask  = (const float*)d_in[0];
    const float* x     = (const float*)d_in[1];
    const float* w1    = (const float*)d_in[2];
    const float* b1    = (const float*)d_in[3];
    const float* w_off = (const float*)d_in[4];
    const float* w_dcn = (const float*)d_in[5];
    const float* b_dcn = (const float*)d_in[6];
    const float* w2    = (const float*)d_in[7];
    const float* b2    = (const float*)d_in[8];
    const float* fc1_w = (const float*)d_in[9];
    const float* fc1_b = (const float*)d_in[10];
    const float* fc2_w = (const float*)d_in[11];
    const float* fc2_b = (const float*)d_in[12];
    const float* io_w  = (const float*)d_in[13];
    const float* io_b  = (const float*)d_in[14];
    float* out = (float*)d_out;

    // launch 1: conv1
    dim3 g1(4, 16, 128), b1d(32, 8);
    conv1_kernel<<<g1, b1d>>>(x, mask, w1, b1);

    // launches 2,3: spacers so dcn is our 4th launch (= ncu capture window)
    noop_kernel<<<1, 32>>>();
    noop_kernel<<<1, 32>>>();

    // launch 4: dcn (profiled next round)
    size_t smem = 33298 * sizeof(float);  // 133,192 B
    cudaFuncSetAttribute(dcn_kernel, cudaFuncAttributeMaxDynamicSharedMemorySize,
                         (int)(136 * 1024));
    dcn_kernel<<<128, 512, smem>>>(w_off, w_dcn, b_dcn, w2, b2);

    float* feat_p;  cudaGetSymbolAddress((void**)&feat_p,  g_feat);
    float* act1_p;  cudaGetSymbolAddress((void**)&act1_p,  g_act1);
    float* part1_p; cudaGetSymbolAddress((void**)&part1_p, g_part1);
    float* part2_p; cudaGetSymbolAddress((void**)&part2_p, g_part2);

    gemm_tf32_kernel<2048, 1024, 8192><<<dim3(16, 8), 256>>>(feat_p, fc1_w, part1_p);
    act1_kernel<<<NB * 2048 / 256, 256>>>(fc1_b);
    gemm_tf32_kernel<1024, 128, 2048><<<dim3(8, 16), 256>>>(act1_p, fc2_w, part2_p);
    io_kernel<<<128, 256>>>(fc2_b, io_w, io_b, out);
}

// round 10
// speedup vs baseline: 1.3384x; 1.3384x over previous
#include <cuda_runtime.h>
#include <math.h>
#include <stdint.h>

typedef unsigned long long ull;

#define NB 128
#define HH 128
#define WW 128

// ---------------- packed fp32x2 helpers (sm_100+) ----------------
__device__ __forceinline__ ull fma2(ull a, ull b, ull c) {
    ull d;
    asm("fma.rn.f32x2 %0, %1, %2, %3;" : "=l"(d) : "l"(a), "l"(b), "l"(c));
    return d;
}
__device__ __forceinline__ ull pack2(float lo, float hi) {
    return ((ull)__float_as_uint(hi) << 32) | (ull)__float_as_uint(lo);
}
__device__ __forceinline__ float sum2(ull v) {
    return __uint_as_float((unsigned)v) + __uint_as_float((unsigned)(v >> 32));
}

// tf32 round (rna)
__device__ __forceinline__ float f2tf(float f) {
    uint32_t r;
    asm("cvt.rna.tf32.f32 %0, %1;" : "=r"(r) : "f"(f));
    return __uint_as_float(r);
}

// ---------------- scratch (static device arrays; no allocs) ----------------
__device__ float g_h[NB * 2 * HH * WW];        // 16 MB: conv1 output
__device__ float g_feat[NB * 8192];            // pooled features (f32)
__device__ float g_part1[8 * NB * 2048];       // fc1 split-K partials
__device__ float g_act1[NB * 2048];            // relu(fc1+b)
__device__ float g_part2[16 * NB * 1024];      // fc2 split-K partials

// ---------------- no-op spacers: align dcn to ncu's capture window ----------
__global__ void noop_kernel() {
    if (blockIdx.x == 0xFFFFFFFFu) g_act1[0] = 0.f;  // never taken
}

// ---------------- conv1: z=concat(x,mask), 3x3 pad1, 9->2 ch ----------------
__global__ void __launch_bounds__(256) conv1_kernel(
    const float* __restrict__ x, const float* __restrict__ mask,
    const float* __restrict__ w1, const float* __restrict__ b1)
{
    __shared__ float s[9 * 10 * 34];
    __shared__ float ws[162];
    __shared__ float bs[2];
    int n = blockIdx.z;
    int ty0 = blockIdx.y * 8, tx0 = blockIdx.x * 32;
    int tid = threadIdx.y * 32 + threadIdx.x;
    if (tid < 162) ws[tid] = w1[tid];
    if (tid < 2) bs[tid] = b1[tid];
    for (int i = tid; i < 9 * 340; i += 256) {
        int c = i / 340, rem = i % 340;
        int yy = rem / 34, xx = rem % 34;
        int gy = ty0 + yy - 1, gx = tx0 + xx - 1;
        float v = 0.f;
        if (gy >= 0 && gy < HH && gx >= 0 && gx < WW)
            v = (c < 8) ? x[((n * 8 + c) * HH + gy) * WW + gx]
                        : mask[(n * HH + gy) * WW + gx];
        s[i] = v;
    }
    __syncthreads();
    int ty = threadIdx.y, tx = threadIdx.x;
    float a0 = bs[0], a1 = bs[1];
#pragma unroll
    for (int c = 0; c < 9; c++)
#pragma unroll
        for (int ky = 0; ky < 3; ky++)
#pragma unroll
            for (int kx = 0; kx < 3; kx++) {
                float v = s[c * 340 + (ty + ky) * 34 + (tx + kx)];
                a0 += v * ws[(0 * 9 + c) * 9 + ky * 3 + kx];
                a1 += v * ws[(1 * 9 + c) * 9 + ky * 3 + kx];
            }
    int oy = ty0 + ty, ox = tx0 + tx;
    g_h[((n * 2 + 0) * HH + oy) * WW + ox] = a0;
    g_h[((n * 2 + 1) * HH + oy) * WW + ox] = a1;
}

// ---------------- fused DCN stage: one CTA per image, 512 threads -------------
// __launch_bounds__(512, 1): minBlocks=1 unlocks the full 128-reg/thread budget
// (ptxas's default heuristic picked 64 regs and spilled ~2.4 GB to local).
__global__ void __launch_bounds__(512, 1) dcn_kernel(
    const float* __restrict__ w_off, const float* __restrict__ w_dcn,
    const float* __restrict__ b_dcn, const float* __restrict__ w2,
    const float* __restrict__ b2)
{
    extern __shared__ float sm[];
    float* hs  = sm;            // 32768 floats (2 x 128 x 128)
    float* wof = sm + 32768;    // 486
    float* wd  = wof + 486;     // 36
    float* w2s = wd + 36;       // 4
    float* bds = w2s + 4;       // 2
    float* b2s = bds + 2;       // 2
    int n = blockIdx.x;
    int tid = threadIdx.x;  // 512

    const float4* src = (const float4*)(g_h + n * 32768);
    float4* dst = (float4*)hs;
    for (int i = tid; i < 8192; i += 512) dst[i] = src[i];
    if (tid < 486) wof[tid] = w_off[tid];
    if (tid < 36) wd[tid] = w_dcn[tid];
    if (tid < 4) w2s[tid] = w2[tid];
    if (tid < 2) { bds[tid] = b_dcn[tid]; b2s[tid] = b2[tid]; }
    __syncthreads();

    const ull* wof2 = (const ull*)wof;

#pragma unroll 1
    for (int idx = tid; idx < 4096; idx += 512) {
        int py = idx >> 6, px = idx & 63;
        float m0 = -1e30f, m1 = -1e30f;
#pragma unroll 1
        for (int sub = 0; sub < 4; sub++) {
            int y = py * 2 + (sub >> 1);
            int x = px * 2 + (sub & 1);

            // gather the 18 dilated taps of h around (y,x)
            float t[18];
            if (y >= 3 && y < HH - 3 && x >= 3 && x < WW - 3) {
                const float* p = hs + y * 128 + x;
#pragma unroll
                for (int c = 0; c < 2; c++)
#pragma unroll
                    for (int j = 0; j < 9; j++)
                        t[c * 9 + j] = p[c * 16384 + (j / 3 - 1) * 384 + (j % 3 - 1) * 3];
            } else {
#pragma unroll
                for (int c = 0; c < 2; c++)
#pragma unroll
                    for (int j = 0; j < 9; j++) {
                        int yy = y + (j / 3 - 1) * 3;
                        int xx = x + (j % 3 - 1) * 3;
                        float v = 0.f;
                        if (yy >= 0 && yy < HH && xx >= 0 && xx < WW)
                            v = hs[c * 16384 + yy * 128 + xx];
                        t[c * 9 + j] = v;
                    }
            }
            ull t2[9];
#pragma unroll
            for (int p = 0; p < 9; p++) t2[p] = pack2(t[2 * p], t[2 * p + 1]);

            float a0 = bds[0], a1 = bds[1];
#pragma unroll
            for (int k = 0; k < 9; k++) {
                // lazy offset-conv: channels 2k (dy), 2k+1 (dx), 18+k (mask)
                const ull* wy = wof2 + (2 * k) * 9;
                const ull* wx = wof2 + (2 * k + 1) * 9;
                const ull* wM = wof2 + (18 + k) * 9;
                ull accY = 0ull, accX = 0ull, accM = 0ull;
#pragma unroll
                for (int p = 0; p < 9; p++) {
                    accY = fma2(t2[p], wy[p], accY);
                    accX = fma2(t2[p], wx[p], accX);
                    accM = fma2(t2[p], wM[p], accM);
                }
                float fy = sum2(accY) + (float)(y + (k / 3 - 1) * 3);
                float fx = sum2(accX) + (float)(x + (k % 3 - 1) * 3);
                float mmk = 1.f / (1.f + __expf(-sum2(accM)));

                float y0f = floorf(fy), x0f = floorf(fx);
                int iy0 = (int)y0f, ix0 = (int)x0f;
                float ly = fy - y0f, lx = fx - x0f;
                float c00 = (1.f - ly) * (1.f - lx), c01 = (1.f - ly) * lx;
                float c10 = ly * (1.f - lx),         c11 = ly * lx;
                bool vy0 = (iy0 >= 0) && (iy0 < HH);
                bool vy1 = (iy0 + 1 >= 0) && (iy0 + 1 < HH);
                bool vx0 = (ix0 >= 0) && (ix0 < WW);
                bool vx1 = (ix0 + 1 >= 0) && (ix0 + 1 < WW);
                int cy0 = min(max(iy0, 0), HH - 1), cy1 = min(max(iy0 + 1, 0), HH - 1);
                int cx0 = min(max(ix0, 0), WW - 1), cx1 = min(max(ix0 + 1, 0), WW - 1);
#pragma unroll
                for (int c = 0; c < 2; c++) {
                    const float* hb = hs + c * 16384;
                    float v00 = (vy0 && vx0) ? hb[cy0 * 128 + cx0] : 0.f;
                    float v01 = (vy0 && vx1) ? hb[cy0 * 128 + cx1] : 0.f;
                    float v10 = (vy1 && vx0) ? hb[cy1 * 128 + cx0] : 0.f;
                    float v11 = (vy1 && vx1) ? hb[cy1 * 128 + cx1] : 0.f;
                    float sc = (v00 * c00 + v01 * c01 + v10 * c10 + v11 * c11) * mmk;
                    a0 += sc * wd[0 * 18 + c * 9 + k];
                    a1 += sc * wd[1 * 18 + c * 9 + k];
                }
            }
            float o0 = fmaxf(a0 * w2s[0] + a1 * w2s[1] + b2s[0], 0.f);
            float o1 = fmaxf(a0 * w2s[2] + a1 * w2s[3] + b2s[1], 0.f);
            m0 = fmaxf(m0, o0);
            m1 = fmaxf(m1, o1);
        }
        g_feat[n * 8192 + idx]        = m0;   // channel 0
        g_feat[n * 8192 + 4096 + idx] = m1;   // channel 1
    }
}

// ---------------- tf32 tensor-core GEMM: C_part = A(128 x LDK) @ B^T ----------
__device__ __forceinline__ void mma_tf32(float4& c, const uint32_t* a,
                                         uint32_t b0, uint32_t b1) {
    asm volatile(
        "mma.sync.aligned.m16n8k8.row.col.f32.tf32.tf32.f32 "
        "{%0,%1,%2,%3}, {%4,%5,%6,%7}, {%8,%9}, {%0,%1,%2,%3};\n"
        : "+f"(c.x), "+f"(c.y), "+f"(c.z), "+f"(c.w)
        : "r"(a[0]), "r"(a[1]), "r"(a[2]), "r"(a[3]), "r"(b0), "r"(b1));
}

template <int NTOT, int KCH, int LDK>
__global__ void __launch_bounds__(256) gemm_tf32_kernel(
    const float* __restrict__ A, const float* __restrict__ B,
    float* __restrict__ part)
{
    __shared__ float As[128 * 36];
    __shared__ float Bs[128 * 36];
    int ntile = blockIdx.x, kz = blockIdx.y;
    int tid = threadIdx.x;
    int warp = tid >> 5, lane = tid & 31;
    int g = lane >> 2, t = lane & 3;
    int wm = warp >> 1, wn = warp & 1;

    float4 acc[2][8];
#pragma unroll
    for (int i = 0; i < 2; i++)
#pragma unroll
        for (int j = 0; j < 8; j++) acc[i][j] = make_float4(0.f, 0.f, 0.f, 0.f);

    int k0base = kz * KCH;
    for (int s = 0; s < KCH; s += 32) {
        int k0 = k0base + s;
#pragma unroll
        for (int i = 0; i < 4; i++) {
            int lin = tid + i * 256;           // 0..1023
            int row = lin >> 3, cw = (lin & 7) * 4;
            float4 va = *(const float4*)&A[row * LDK + k0 + cw];
            float4 vb = *(const float4*)&B[(ntile * 128 + row) * LDK + k0 + cw];
            float4 ta = make_float4(f2tf(va.x), f2tf(va.y), f2tf(va.z), f2tf(va.w));
            float4 tb = make_float4(f2tf(vb.x), f2tf(vb.y), f2tf(vb.z), f2tf(vb.w));
            *(float4*)&As[row * 36 + cw] = ta;
            *(float4*)&Bs[row * 36 + cw] = tb;
        }
        __syncthreads();
#pragma unroll
        for (int kk = 0; kk < 32; kk += 8) {
            uint32_t a[2][4];
#pragma unroll
            for (int im = 0; im < 2; im++) {
                int r = wm * 32 + im * 16 + g;
                a[im][0] = __float_as_uint(As[r * 36 + kk + t]);
                a[im][1] = __float_as_uint(As[(r + 8) * 36 + kk + t]);
                a[im][2] = __float_as_uint(As[r * 36 + kk + t + 4]);
                a[im][3] = __float_as_uint(As[(r + 8) * 36 + kk + t + 4]);
            }
#pragma unroll
            for (int jn = 0; jn < 8; jn++) {
                int rb = wn * 64 + jn * 8 + g;
                uint32_t b0 = __float_as_uint(Bs[rb * 36 + kk + t]);
                uint32_t b1 = __float_as_uint(Bs[rb * 36 + kk + t + 4]);
                mma_tf32(acc[0][jn], a[0], b0, b1);
                mma_tf32(acc[1][jn], a[1], b0, b1);
            }
        }
        __syncthreads();
    }

    float* P = part + (size_t)kz * 128 * NTOT;
#pragma unroll
    for (int im = 0; im < 2; im++)
#pragma unroll
        for (int jn = 0; jn < 8; jn++) {
            int r0 = wm * 32 + im * 16 + g;
            int col = ntile * 128 + wn * 64 + jn * 8 + 2 * t;
            float4 c = acc[im][jn];
            *(float2*)&P[r0 * NTOT + col]       = make_float2(c.x, c.y);
            *(float2*)&P[(r0 + 8) * NTOT + col] = make_float2(c.z, c.w);
        }
}

// ---------------- act1: reduce fc1 partials + bias + relu ----------------
__global__ void __launch_bounds__(256) act1_kernel(const float* __restrict__ fc1_b) {
    int i = blockIdx.x * 256 + threadIdx.x;   // 0 .. 128*2048-1
    float v = fc1_b[i & 2047];
#pragma unroll
    for (int kz = 0; kz < 8; kz++) v += g_part1[kz * (NB * 2048) + i];
    g_act1[i] = fmaxf(v, 0.f);
}

// ---------------- final: reduce fc2 partials + bias + relu, dot io_w, sigmoid --
__global__ void __launch_bounds__(256) io_kernel(
    const float* __restrict__ fc2_b, const float* __restrict__ io_w,
    const float* __restrict__ io_b, float* __restrict__ out)
{
    int n = blockIdx.x;
    int tid = threadIdx.x;
    float s = 0.f;
    for (int k = tid; k < 1024; k += 256) {
        float v = fc2_b[k];
#pragma unroll
        for (int kz = 0; kz < 16; kz++)
            v += g_part2[kz * (NB * 1024) + n * 1024 + k];
        s += fmaxf(v, 0.f) * io_w[k];
    }
#pragma unroll
    for (int o = 16; o > 0; o >>= 1) s += __shfl_down_sync(0xffffffffu, s, o);
    __shared__ float red[8];
    if ((tid & 31) == 0) red[tid >> 5] = s;
    __syncthreads();
    if (tid == 0) {
        float tt = 0.f;
#pragma unroll
        for (int i = 0; i < 8; i++) tt += red[i];
        out[n] = 1.f / (1.f + __expf(-(tt + io_b[0])));
    }
}

extern "C" void kernel_launch(void* const* d_in, const int* in_sizes, int n_in,
                              void* d_out, int out_size) {
    const float* mask  = (const float*)d_in[0];
    const float* x     = (const float*)d_in[1];
    const float* w1    = (const float*)d_in[2];
    const float* b1    = (const float*)d_in[3];
    const float* w_off = (const float*)d_in[4];
    const float* w_dcn = (const float*)d_in[5];
    const float* b_dcn = (const float*)d_in[6];
    const float* w2    = (const float*)d_in[7];
    const float* b2    = (const float*)d_in[8];
    const float* fc1_w = (const float*)d_in[9];
    const float* fc1_b = (const float*)d_in[10];
    const float* fc2_w = (const float*)d_in[11];
    const float* fc2_b = (const float*)d_in[12];
    const float* io_w  = (const float*)d_in[13];
    const float* io_b  = (const float*)d_in[14];
    float* out = (float*)d_out;

    // launch 1: conv1
    dim3 g1(4, 16, 128), b1d(32, 8);
    conv1_kernel<<<g1, b1d>>>(x, mask, w1, b1);

    // launches 2,3: spacers so dcn is our 4th launch (= ncu capture window)
    noop_kernel<<<1, 32>>>();
    noop_kernel<<<1, 32>>>();

    // launch 4: dcn (profiled)
    size_t smem = 33298 * sizeof(float);  // 133,192 B
    cudaFuncSetAttribute(dcn_kernel, cudaFuncAttributeMaxDynamicSharedMemorySize,
                         (int)(136 * 1024));
    dcn_kernel<<<128, 512, smem>>>(w_off, w_dcn, b_dcn, w2, b2);

    float* feat_p;  cudaGetSymbolAddress((void**)&feat_p,  g_feat);
    float* act1_p;  cudaGetSymbolAddress((void**)&act1_p,  g_act1);
    float* part1_p; cudaGetSymbolAddress((void**)&part1_p, g_part1);
    float* part2_p; cudaGetSymbolAddress((void**)&part2_p, g_part2);

    gemm_tf32_kernel<2048, 1024, 8192><<<dim3(16, 8), 256>>>(feat_p, fc1_w, part1_p);
    act1_kernel<<<NB * 2048 / 256, 256>>>(fc1_b);
    gemm_tf32_kernel<1024, 128, 2048><<<dim3(8, 16), 256>>>(act1_p, fc2_w, part2_p);
    io_kernel<<<128, 256>>>(fc2_b, io_w, io_b, out);
}

// round 11
// speedup vs baseline: 1.4737x; 1.1011x over previous
#include <cuda_runtime.h>
#include <math.h>
#include <stdint.h>

typedef unsigned long long ull;

#define NB 128
#define HH 128
#define WW 128

// ---------------- packed fp32x2 helpers (sm_100+) ----------------
__device__ __forceinline__ ull fma2(ull a, ull b, ull c) {
    ull d;
    asm("fma.rn.f32x2 %0, %1, %2, %3;" : "=l"(d) : "l"(a), "l"(b), "l"(c));
    return d;
}
__device__ __forceinline__ ull pack2(float lo, float hi) {
    return ((ull)__float_as_uint(hi) << 32) | (ull)__float_as_uint(lo);
}
__device__ __forceinline__ float sum2(ull v) {
    return __uint_as_float((unsigned)v) + __uint_as_float((unsigned)(v >> 32));
}

// tf32 round (rna)
__device__ __forceinline__ float f2tf(float f) {
    uint32_t r;
    asm("cvt.rna.tf32.f32 %0, %1;" : "=r"(r) : "f"(f));
    return __uint_as_float(r);
}

// ---------------- scratch (static device arrays; no allocs) ----------------
__device__ float g_h[NB * 2 * HH * WW];        // 16 MB: conv1 output
__device__ float g_feat[NB * 8192];            // pooled features (f32)
__device__ float g_part1[8 * NB * 2048];       // fc1 split-K partials
__device__ float g_act1[NB * 2048];            // relu(fc1+b)
__device__ float g_part2[16 * NB * 1024];      // fc2 split-K partials

// ---------------- no-op spacers: align dcn to ncu's capture window ----------
__global__ void noop_kernel() {
    if (blockIdx.x == 0xFFFFFFFFu) g_act1[0] = 0.f;  // never taken
}

// ---------------- conv1: z=concat(x,mask), 3x3 pad1, 9->2 ch ----------------
__global__ void __launch_bounds__(256) conv1_kernel(
    const float* __restrict__ x, const float* __restrict__ mask,
    const float* __restrict__ w1, const float* __restrict__ b1)
{
    __shared__ float s[9 * 10 * 34];
    __shared__ float ws[162];
    __shared__ float bs[2];
    int n = blockIdx.z;
    int ty0 = blockIdx.y * 8, tx0 = blockIdx.x * 32;
    int tid = threadIdx.y * 32 + threadIdx.x;
    if (tid < 162) ws[tid] = w1[tid];
    if (tid < 2) bs[tid] = b1[tid];
    for (int i = tid; i < 9 * 340; i += 256) {
        int c = i / 340, rem = i % 340;
        int yy = rem / 34, xx = rem % 34;
        int gy = ty0 + yy - 1, gx = tx0 + xx - 1;
        float v = 0.f;
        if (gy >= 0 && gy < HH && gx >= 0 && gx < WW)
            v = (c < 8) ? x[((n * 8 + c) * HH + gy) * WW + gx]
                        : mask[(n * HH + gy) * WW + gx];
        s[i] = v;
    }
    __syncthreads();
    int ty = threadIdx.y, tx = threadIdx.x;
    float a0 = bs[0], a1 = bs[1];
#pragma unroll
    for (int c = 0; c < 9; c++)
#pragma unroll
        for (int ky = 0; ky < 3; ky++)
#pragma unroll
            for (int kx = 0; kx < 3; kx++) {
                float v = s[c * 340 + (ty + ky) * 34 + (tx + kx)];
                a0 += v * ws[(0 * 9 + c) * 9 + ky * 3 + kx];
                a1 += v * ws[(1 * 9 + c) * 9 + ky * 3 + kx];
            }
    int oy = ty0 + ty, ox = tx0 + tx;
    g_h[((n * 2 + 0) * HH + oy) * WW + ox] = a0;
    g_h[((n * 2 + 1) * HH + oy) * WW + ox] = a1;
}

// ---------------- fused DCN stage: one CTA per image, 384 threads -------------
// 384 thr x (384,1) => ptxas cap 168 regs/thread: fits the ~160-reg live set
// (512 thr capped at 128 and spilled ~1 GB to local; measured R10).
__global__ void __launch_bounds__(384, 1) dcn_kernel(
    const float* __restrict__ w_off, const float* __restrict__ w_dcn,
    const float* __restrict__ b_dcn, const float* __restrict__ w2,
    const float* __restrict__ b2)
{
    extern __shared__ float sm[];
    float* hs  = sm;            // 32768 floats (2 x 128 x 128)
    float* wof = sm + 32768;    // 486
    float* wd  = wof + 486;     // 36
    float* w2s = wd + 36;       // 4
    float* bds = w2s + 4;       // 2
    float* b2s = bds + 2;       // 2
    int n = blockIdx.x;
    int tid = threadIdx.x;  // 384

    const float4* src = (const float4*)(g_h + n * 32768);
    float4* dst = (float4*)hs;
    for (int i = tid; i < 8192; i += 384) dst[i] = src[i];
    if (tid < 486 && tid >= 0) wof[tid] = w_off[tid];
    if (tid < 486 - 384) wof[384 + tid] = w_off[384 + tid];
    if (tid < 36) wd[tid] = w_dcn[tid];
    if (tid < 4) w2s[tid] = w2[tid];
    if (tid < 2) { bds[tid] = b_dcn[tid]; b2s[tid] = b2[tid]; }
    __syncthreads();

    const ull* wof2 = (const ull*)wof;

#pragma unroll 1
    for (int idx = tid; idx < 4096; idx += 384) {
        int py = idx >> 6, px = idx & 63;
        float m0 = -1e30f, m1 = -1e30f;
#pragma unroll 1
        for (int sub = 0; sub < 4; sub++) {
            int y = py * 2 + (sub >> 1);
            int x = px * 2 + (sub & 1);

            // gather the 18 dilated taps of h around (y,x)
            float t[18];
            if (y >= 3 && y < HH - 3 && x >= 3 && x < WW - 3) {
                const float* p = hs + y * 128 + x;
#pragma unroll
                for (int c = 0; c < 2; c++)
#pragma unroll
                    for (int j = 0; j < 9; j++)
                        t[c * 9 + j] = p[c * 16384 + (j / 3 - 1) * 384 + (j % 3 - 1) * 3];
            } else {
#pragma unroll
                for (int c = 0; c < 2; c++)
#pragma unroll
                    for (int j = 0; j < 9; j++) {
                        int yy = y + (j / 3 - 1) * 3;
                        int xx = x + (j % 3 - 1) * 3;
                        float v = 0.f;
                        if (yy >= 0 && yy < HH && xx >= 0 && xx < WW)
                            v = hs[c * 16384 + yy * 128 + xx];
                        t[c * 9 + j] = v;
                    }
            }
            ull t2[9];
#pragma unroll
            for (int p = 0; p < 9; p++) t2[p] = pack2(t[2 * p], t[2 * p + 1]);

            float a0 = bds[0], a1 = bds[1];
#pragma unroll
            for (int k = 0; k < 9; k++) {
                // lazy offset-conv: channels 2k (dy), 2k+1 (dx), 18+k (mask)
                const ull* wy = wof2 + (2 * k) * 9;
                const ull* wx = wof2 + (2 * k + 1) * 9;
                const ull* wM = wof2 + (18 + k) * 9;
                ull accY = 0ull, accX = 0ull, accM = 0ull;
#pragma unroll
                for (int p = 0; p < 9; p++) {
                    accY = fma2(t2[p], wy[p], accY);
                    accX = fma2(t2[p], wx[p], accX);
                    accM = fma2(t2[p], wM[p], accM);
                }
                float fy = sum2(accY) + (float)(y + (k / 3 - 1) * 3);
                float fx = sum2(accX) + (float)(x + (k % 3 - 1) * 3);
                float mmk = 1.f / (1.f + __expf(-sum2(accM)));

                float y0f = floorf(fy), x0f = floorf(fx);
                int iy0 = (int)y0f, ix0 = (int)x0f;
                float ly = fy - y0f, lx = fx - x0f;
                float c00 = (1.f - ly) * (1.f - lx), c01 = (1.f - ly) * lx;
                float c10 = ly * (1.f - lx),         c11 = ly * lx;
                bool vy0 = (iy0 >= 0) && (iy0 < HH);
                bool vy1 = (iy0 + 1 >= 0) && (iy0 + 1 < HH);
                bool vx0 = (ix0 >= 0) && (ix0 < WW);
                bool vx1 = (ix0 + 1 >= 0) && (ix0 + 1 < WW);
                int cy0 = min(max(iy0, 0), HH - 1), cy1 = min(max(iy0 + 1, 0), HH - 1);
                int cx0 = min(max(ix0, 0), WW - 1), cx1 = min(max(ix0 + 1, 0), WW - 1);
#pragma unroll
                for (int c = 0; c < 2; c++) {
                    const float* hb = hs + c * 16384;
                    float v00 = (vy0 && vx0) ? hb[cy0 * 128 + cx0] : 0.f;
                    float v01 = (vy0 && vx1) ? hb[cy0 * 128 + cx1] : 0.f;
                    float v10 = (vy1 && vx0) ? hb[cy1 * 128 + cx0] : 0.f;
                    float v11 = (vy1 && vx1) ? hb[cy1 * 128 + cx1] : 0.f;
                    float sc = (v00 * c00 + v01 * c01 + v10 * c10 + v11 * c11) * mmk;
                    a0 += sc * wd[0 * 18 + c * 9 + k];
                    a1 += sc * wd[1 * 18 + c * 9 + k];
                }
            }
            float o0 = fmaxf(a0 * w2s[0] + a1 * w2s[1] + b2s[0], 0.f);
            float o1 = fmaxf(a0 * w2s[2] + a1 * w2s[3] + b2s[1], 0.f);
            m0 = fmaxf(m0, o0);
            m1 = fmaxf(m1, o1);
        }
        g_feat[n * 8192 + idx]        = m0;   // channel 0
        g_feat[n * 8192 + 4096 + idx] = m1;   // channel 1
    }
}

// ---------------- tf32 tensor-core GEMM: C_part = A(128 x LDK) @ B^T ----------
__device__ __forceinline__ void mma_tf32(float4& c, const uint32_t* a,
                                         uint32_t b0, uint32_t b1) {
    asm volatile(
        "mma.sync.aligned.m16n8k8.row.col.f32.tf32.tf32.f32 "
        "{%0,%1,%2,%3}, {%4,%5,%6,%7}, {%8,%9}, {%0,%1,%2,%3};\n"
        : "+f"(c.x), "+f"(c.y), "+f"(c.z), "+f"(c.w)
        : "r"(a[0]), "r"(a[1]), "r"(a[2]), "r"(a[3]), "r"(b0), "r"(b1));
}

template <int NTOT, int KCH, int LDK>
__global__ void __launch_bounds__(256) gemm_tf32_kernel(
    const float* __restrict__ A, const float* __restrict__ B,
    float* __restrict__ part)
{
    __shared__ float As[128 * 36];
    __shared__ float Bs[128 * 36];
    int ntile = blockIdx.x, kz = blockIdx.y;
    int tid = threadIdx.x;
    int warp = tid >> 5, lane = tid & 31;
    int g = lane >> 2, t = lane & 3;
    int wm = warp >> 1, wn = warp & 1;

    float4 acc[2][8];
#pragma unroll
    for (int i = 0; i < 2; i++)
#pragma unroll
        for (int j = 0; j < 8; j++) acc[i][j] = make_float4(0.f, 0.f, 0.f, 0.f);

    int k0base = kz * KCH;
    for (int s = 0; s < KCH; s += 32) {
        int k0 = k0base + s;
#pragma unroll
        for (int i = 0; i < 4; i++) {
            int lin = tid + i * 256;           // 0..1023
            int row = lin >> 3, cw = (lin & 7) * 4;
            float4 va = *(const float4*)&A[row * LDK + k0 + cw];
            float4 vb = *(const float4*)&B[(ntile * 128 + row) * LDK + k0 + cw];
            float4 ta = make_float4(f2tf(va.x), f2tf(va.y), f2tf(va.z), f2tf(va.w));
            float4 tb = make_float4(f2tf(vb.x), f2tf(vb.y), f2tf(vb.z), f2tf(vb.w));
            *(float4*)&As[row * 36 + cw] = ta;
            *(float4*)&Bs[row * 36 + cw] = tb;
        }
        __syncthreads();
#pragma unroll
        for (int kk = 0; kk < 32; kk += 8) {
            uint32_t a[2][4];
#pragma unroll
            for (int im = 0; im < 2; im++) {
                int r = wm * 32 + im * 16 + g;
                a[im][0] = __float_as_uint(As[r * 36 + kk + t]);
                a[im][1] = __float_as_uint(As[(r + 8) * 36 + kk + t]);
                a[im][2] = __float_as_uint(As[r * 36 + kk + t + 4]);
                a[im][3] = __float_as_uint(As[(r + 8) * 36 + kk + t + 4]);
            }
#pragma unroll
            for (int jn = 0; jn < 8; jn++) {
                int rb = wn * 64 + jn * 8 + g;
                uint32_t b0 = __float_as_uint(Bs[rb * 36 + kk + t]);
                uint32_t b1 = __float_as_uint(Bs[rb * 36 + kk + t + 4]);
                mma_tf32(acc[0][jn], a[0], b0, b1);
                mma_tf32(acc[1][jn], a[1], b0, b1);
            }
        }
        __syncthreads();
    }

    float* P = part + (size_t)kz * 128 * NTOT;
#pragma unroll
    for (int im = 0; im < 2; im++)
#pragma unroll
        for (int jn = 0; jn < 8; jn++) {
            int r0 = wm * 32 + im * 16 + g;
            int col = ntile * 128 + wn * 64 + jn * 8 + 2 * t;
            float4 c = acc[im][jn];
            *(float2*)&P[r0 * NTOT + col]       = make_float2(c.x, c.y);
            *(float2*)&P[(r0 + 8) * NTOT + col] = make_float2(c.z, c.w);
        }
}

// ---------------- act1: reduce fc1 partials + bias + relu ----------------
__global__ void __launch_bounds__(256) act1_kernel(const float* __restrict__ fc1_b) {
    int i = blockIdx.x * 256 + threadIdx.x;   // 0 .. 128*2048-1
    float v = fc1_b[i & 2047];
#pragma unroll
    for (int kz = 0; kz < 8; kz++) v += g_part1[kz * (NB * 2048) + i];
    g_act1[i] = fmaxf(v, 0.f);
}

// ---------------- final: reduce fc2 partials + bias + relu, dot io_w, sigmoid --
__global__ void __launch_bounds__(256) io_kernel(
    const float* __restrict__ fc2_b, const float* __restrict__ io_w,
    const float* __restrict__ io_b, float* __restrict__ out)
{
    int n = blockIdx.x;
    int tid = threadIdx.x;
    float s = 0.f;
    for (int k = tid; k < 1024; k += 256) {
        float v = fc2_b[k];
#pragma unroll
        for (int kz = 0; kz < 16; kz++)
            v += g_part2[kz * (NB * 1024) + n * 1024 + k];
        s += fmaxf(v, 0.f) * io_w[k];
    }
#pragma unroll
    for (int o = 16; o > 0; o >>= 1) s += __shfl_down_sync(0xffffffffu, s, o);
    __shared__ float red[8];
    if ((tid & 31) == 0) red[tid >> 5] = s;
    __syncthreads();
    if (tid == 0) {
        float tt = 0.f;
#pragma unroll
        for (int i = 0; i < 8; i++) tt += red[i];
        out[n] = 1.f / (1.f + __expf(-(tt + io_b[0])));
    }
}

extern "C" void kernel_launch(void* const* d_in, const int* in_sizes, int n_in,
                              void* d_out, int out_size) {
    const float* mask  = (const float*)d_in[0];
    const float* x     = (const float*)d_in[1];
    const float* w1    = (const float*)d_in[2];
    const float* b1    = (const float*)d_in[3];
    const float* w_off = (const float*)d_in[4];
    const float* w_dcn = (const float*)d_in[5];
    const float* b_dcn = (const float*)d_in[6];
    const float* w2    = (const float*)d_in[7];
    const float* b2    = (const float*)d_in[8];
    const float* fc1_w = (const float*)d_in[9];
    const float* fc1_b = (const float*)d_in[10];
    const float* fc2_w = (const float*)d_in[11];
    const float* fc2_b = (const float*)d_in[12];
    const float* io_w  = (const float*)d_in[13];
    const float* io_b  = (const float*)d_in[14];
    float* out = (float*)d_out;

    // launch 1: conv1
    dim3 g1(4, 16, 128), b1d(32, 8);
    conv1_kernel<<<g1, b1d>>>(x, mask, w1, b1);

    // launches 2,3: spacers so dcn is our 4th launch (= ncu capture window)
    noop_kernel<<<1, 32>>>();
    noop_kernel<<<1, 32>>>();

    // launch 4: dcn (profiled)
    size_t smem = 33298 * sizeof(float);  // 133,192 B
    cudaFuncSetAttribute(dcn_kernel, cudaFuncAttributeMaxDynamicSharedMemorySize,
                         (int)(136 * 1024));
    dcn_kernel<<<128, 384, smem>>>(w_off, w_dcn, b_dcn, w2, b2);

    float* feat_p;  cudaGetSymbolAddress((void**)&feat_p,  g_feat);
    float* act1_p;  cudaGetSymbolAddress((void**)&act1_p,  g_act1);
    float* part1_p; cudaGetSymbolAddress((void**)&part1_p, g_part1);
    float* part2_p; cudaGetSymbolAddress((void**)&part2_p, g_part2);

    gemm_tf32_kernel<2048, 1024, 8192><<<dim3(16, 8), 256>>>(feat_p, fc1_w, part1_p);
    act1_kernel<<<NB * 2048 / 256, 256>>>(fc1_b);
    gemm_tf32_kernel<1024, 128, 2048><<<dim3(8, 16), 256>>>(act1_p, fc2_w, part2_p);
    io_kernel<<<128, 256>>>(fc2_b, io_w, io_b, out);
}

// round 12
// speedup vs baseline: 3.0485x; 2.0685x over previous
#include <cuda_runtime.h>
#include <math.h>
#include <stdint.h>

typedef unsigned long long ull;

#define NB 128
#define HH 128
#define WW 128

// ---------------- packed fp32x2 helpers (sm_100+) ----------------
__device__ __forceinline__ ull fma2(ull a, ull b, ull c) {
    ull d;
    asm("fma.rn.f32x2 %0, %1, %2, %3;" : "=l"(d) : "l"(a), "l"(b), "l"(c));
    return d;
}
__device__ __forceinline__ ull pack2(float lo, float hi) {
    return ((ull)__float_as_uint(hi) << 32) | (ull)__float_as_uint(lo);
}
__device__ __forceinline__ float sum2(ull v) {
    return __uint_as_float((unsigned)v) + __uint_as_float((unsigned)(v >> 32));
}

// tf32 round (rna)
__device__ __forceinline__ float f2tf(float f) {
    uint32_t r;
    asm("cvt.rna.tf32.f32 %0, %1;" : "=r"(r) : "f"(f));
    return __uint_as_float(r);
}

// ---------------- scratch (static device arrays; no allocs) ----------------
__device__ float g_h[NB * 2 * HH * WW];        // 16 MB: conv1 output
__device__ float g_feat[NB * 8192];            // pooled features (f32)
__device__ float g_part1[8 * NB * 2048];       // fc1 split-K partials
__device__ float g_act1[NB * 2048];            // relu(fc1+b)
__device__ float g_part2[16 * NB * 1024];      // fc2 split-K partials

// ---------------- no-op spacers: align dcn to ncu's capture window ----------
__global__ void noop_kernel() {
    if (blockIdx.x == 0xFFFFFFFFu) g_act1[0] = 0.f;  // never taken
}

// ---------------- conv1: z=concat(x,mask), 3x3 pad1, 9->2 ch ----------------
__global__ void __launch_bounds__(256) conv1_kernel(
    const float* __restrict__ x, const float* __restrict__ mask,
    const float* __restrict__ w1, const float* __restrict__ b1)
{
    __shared__ float s[9 * 10 * 34];
    __shared__ float ws[162];
    __shared__ float bs[2];
    int n = blockIdx.z;
    int ty0 = blockIdx.y * 8, tx0 = blockIdx.x * 32;
    int tid = threadIdx.y * 32 + threadIdx.x;
    if (tid < 162) ws[tid] = w1[tid];
    if (tid < 2) bs[tid] = b1[tid];
    for (int i = tid; i < 9 * 340; i += 256) {
        int c = i / 340, rem = i % 340;
        int yy = rem / 34, xx = rem % 34;
        int gy = ty0 + yy - 1, gx = tx0 + xx - 1;
        float v = 0.f;
        if (gy >= 0 && gy < HH && gx >= 0 && gx < WW)
            v = (c < 8) ? x[((n * 8 + c) * HH + gy) * WW + gx]
                        : mask[(n * HH + gy) * WW + gx];
        s[i] = v;
    }
    __syncthreads();
    int ty = threadIdx.y, tx = threadIdx.x;
    float a0 = bs[0], a1 = bs[1];
#pragma unroll
    for (int c = 0; c < 9; c++)
#pragma unroll
        for (int ky = 0; ky < 3; ky++)
#pragma unroll
            for (int kx = 0; kx < 3; kx++) {
                float v = s[c * 340 + (ty + ky) * 34 + (tx + kx)];
                a0 += v * ws[(0 * 9 + c) * 9 + ky * 3 + kx];
                a1 += v * ws[(1 * 9 + c) * 9 + ky * 3 + kx];
            }
    int oy = ty0 + ty, ox = tx0 + tx;
    g_h[((n * 2 + 0) * HH + oy) * WW + ox] = a0;
    g_h[((n * 2 + 1) * HH + oy) * WW + ox] = a1;
}

// ---------------- fused DCN stage: one CTA per image, 512 threads -------------
// 512 thr @ (512,1): 128-reg cap. k-loop capped at unroll 3 so the interleaved
// live set (~106 regs) stays under the cap — R10 showed full unroll needs ~160
// and spills; R11 showed the spill-free body wants >128 only due to unrolling.
__global__ void __launch_bounds__(512, 1) dcn_kernel(
    const float* __restrict__ w_off, const float* __restrict__ w_dcn,
    const float* __restrict__ b_dcn, const float* __restrict__ w2,
    const float* __restrict__ b2)
{
    extern __shared__ float sm[];
    float* hs  = sm;            // 32768 floats (2 x 128 x 128)
    float* wof = sm + 32768;    // 486
    float* wd  = wof + 486;     // 36
    float* w2s = wd + 36;       // 4
    float* bds = w2s + 4;       // 2
    float* b2s = bds + 2;       // 2
    int n = blockIdx.x;
    int tid = threadIdx.x;  // 512

    const float4* src = (const float4*)(g_h + n * 32768);
    float4* dst = (float4*)hs;
    for (int i = tid; i < 8192; i += 512) dst[i] = src[i];
    if (tid < 486) wof[tid] = w_off[tid];
    if (tid < 36) wd[tid] = w_dcn[tid];
    if (tid < 4) w2s[tid] = w2[tid];
    if (tid < 2) { bds[tid] = b_dcn[tid]; b2s[tid] = b2[tid]; }
    __syncthreads();

    const ull* wof2 = (const ull*)wof;

#pragma unroll 1
    for (int idx = tid; idx < 4096; idx += 512) {
        int py = idx >> 6, px = idx & 63;
        float m0 = -1e30f, m1 = -1e30f;
#pragma unroll 1
        for (int sub = 0; sub < 4; sub++) {
            int y = py * 2 + (sub >> 1);
            int x = px * 2 + (sub & 1);

            // gather the 18 dilated taps of h around (y,x)
            float t[18];
            if (y >= 3 && y < HH - 3 && x >= 3 && x < WW - 3) {
                const float* p = hs + y * 128 + x;
#pragma unroll
                for (int c = 0; c < 2; c++)
#pragma unroll
                    for (int j = 0; j < 9; j++)
                        t[c * 9 + j] = p[c * 16384 + (j / 3 - 1) * 384 + (j % 3 - 1) * 3];
            } else {
#pragma unroll
                for (int c = 0; c < 2; c++)
#pragma unroll
                    for (int j = 0; j < 9; j++) {
                        int yy = y + (j / 3 - 1) * 3;
                        int xx = x + (j % 3 - 1) * 3;
                        float v = 0.f;
                        if (yy >= 0 && yy < HH && xx >= 0 && xx < WW)
                            v = hs[c * 16384 + yy * 128 + xx];
                        t[c * 9 + j] = v;
                    }
            }
            ull t2[9];
#pragma unroll
            for (int p = 0; p < 9; p++) t2[p] = pack2(t[2 * p], t[2 * p + 1]);

            float a0 = bds[0], a1 = bds[1];
#pragma unroll 3
            for (int k = 0; k < 9; k++) {
                // lazy offset-conv: channels 2k (dy), 2k+1 (dx), 18+k (mask)
                const ull* wy = wof2 + (2 * k) * 9;
                const ull* wx = wof2 + (2 * k + 1) * 9;
                const ull* wM = wof2 + (18 + k) * 9;
                ull accY = 0ull, accX = 0ull, accM = 0ull;
#pragma unroll
                for (int p = 0; p < 9; p++) {
                    accY = fma2(t2[p], wy[p], accY);
                    accX = fma2(t2[p], wx[p], accX);
                    accM = fma2(t2[p], wM[p], accM);
                }
                float fy = sum2(accY) + (float)(y + (k / 3 - 1) * 3);
                float fx = sum2(accX) + (float)(x + (k % 3 - 1) * 3);
                float mmk = 1.f / (1.f + __expf(-sum2(accM)));

                float y0f = floorf(fy), x0f = floorf(fx);
                int iy0 = (int)y0f, ix0 = (int)x0f;
                float ly = fy - y0f, lx = fx - x0f;
                // fold mmk into the bilinear coefficients (once per k, not per c)
                float w00 = (1.f - ly) * (1.f - lx) * mmk, w01 = (1.f - ly) * lx * mmk;
                float w10 = ly * (1.f - lx) * mmk,         w11 = ly * lx * mmk;
                bool vy0 = (iy0 >= 0) && (iy0 < HH);
                bool vy1 = (iy0 + 1 >= 0) && (iy0 + 1 < HH);
                bool vx0 = (ix0 >= 0) && (ix0 < WW);
                bool vx1 = (ix0 + 1 >= 0) && (ix0 + 1 < WW);
                int cy0 = min(max(iy0, 0), HH - 1), cy1 = min(max(iy0 + 1, 0), HH - 1);
                int cx0 = min(max(ix0, 0), WW - 1), cx1 = min(max(ix0 + 1, 0), WW - 1);
                int r0 = cy0 * 128, r1 = cy1 * 128;
#pragma unroll
                for (int c = 0; c < 2; c++) {
                    const float* hb = hs + c * 16384;
                    float v00 = (vy0 && vx0) ? hb[r0 + cx0] : 0.f;
                    float v01 = (vy0 && vx1) ? hb[r0 + cx1] : 0.f;
                    float v10 = (vy1 && vx0) ? hb[r1 + cx0] : 0.f;
                    float v11 = (vy1 && vx1) ? hb[r1 + cx1] : 0.f;
                    float sc = v00 * w00 + v01 * w01 + v10 * w10 + v11 * w11;
                    a0 += sc * wd[0 * 18 + c * 9 + k];
                    a1 += sc * wd[1 * 18 + c * 9 + k];
                }
            }
            float o0 = fmaxf(a0 * w2s[0] + a1 * w2s[1] + b2s[0], 0.f);
            float o1 = fmaxf(a0 * w2s[2] + a1 * w2s[3] + b2s[1], 0.f);
            m0 = fmaxf(m0, o0);
            m1 = fmaxf(m1, o1);
        }
        g_feat[n * 8192 + idx]        = m0;   // channel 0
        g_feat[n * 8192 + 4096 + idx] = m1;   // channel 1
    }
}

// ---------------- tf32 tensor-core GEMM: C_part = A(128 x LDK) @ B^T ----------
__device__ __forceinline__ void mma_tf32(float4& c, const uint32_t* a,
                                         uint32_t b0, uint32_t b1) {
    asm volatile(
        "mma.sync.aligned.m16n8k8.row.col.f32.tf32.tf32.f32 "
        "{%0,%1,%2,%3}, {%4,%5,%6,%7}, {%8,%9}, {%0,%1,%2,%3};\n"
        : "+f"(c.x), "+f"(c.y), "+f"(c.z), "+f"(c.w)
        : "r"(a[0]), "r"(a[1]), "r"(a[2]), "r"(a[3]), "r"(b0), "r"(b1));
}

template <int NTOT, int KCH, int LDK>
__global__ void __launch_bounds__(256) gemm_tf32_kernel(
    const float* __restrict__ A, const float* __restrict__ B,
    float* __restrict__ part)
{
    __shared__ float As[128 * 36];
    __shared__ float Bs[128 * 36];
    int ntile = blockIdx.x, kz = blockIdx.y;
    int tid = threadIdx.x;
    int warp = tid >> 5, lane = tid & 31;
    int g = lane >> 2, t = lane & 3;
    int wm = warp >> 1, wn = warp & 1;

    float4 acc[2][8];
#pragma unroll
    for (int i = 0; i < 2; i++)
#pragma unroll
        for (int j = 0; j < 8; j++) acc[i][j] = make_float4(0.f, 0.f, 0.f, 0.f);

    int k0base = kz * KCH;
    for (int s = 0; s < KCH; s += 32) {
        int k0 = k0base + s;
#pragma unroll
        for (int i = 0; i < 4; i++) {
            int lin = tid + i * 256;           // 0..1023
            int row = lin >> 3, cw = (lin & 7) * 4;
            float4 va = *(const float4*)&A[row * LDK + k0 + cw];
            float4 vb = *(const float4*)&B[(ntile * 128 + row) * LDK + k0 + cw];
            float4 ta = make_float4(f2tf(va.x), f2tf(va.y), f2tf(va.z), f2tf(va.w));
            float4 tb = make_float4(f2tf(vb.x), f2tf(vb.y), f2tf(vb.z), f2tf(vb.w));
            *(float4*)&As[row * 36 + cw] = ta;
            *(float4*)&Bs[row * 36 + cw] = tb;
        }
        __syncthreads();
#pragma unroll
        for (int kk = 0; kk < 32; kk += 8) {
            uint32_t a[2][4];
#pragma unroll
            for (int im = 0; im < 2; im++) {
                int r = wm * 32 + im * 16 + g;
                a[im][0] = __float_as_uint(As[r * 36 + kk + t]);
                a[im][1] = __float_as_uint(As[(r + 8) * 36 + kk + t]);
                a[im][2] = __float_as_uint(As[r * 36 + kk + t + 4]);
                a[im][3] = __float_as_uint(As[(r + 8) * 36 + kk + t + 4]);
            }
#pragma unroll
            for (int jn = 0; jn < 8; jn++) {
                int rb = wn * 64 + jn * 8 + g;
                uint32_t b0 = __float_as_uint(Bs[rb * 36 + kk + t]);
                uint32_t b1 = __float_as_uint(Bs[rb * 36 + kk + t + 4]);
                mma_tf32(acc[0][jn], a[0], b0, b1);
                mma_tf32(acc[1][jn], a[1], b0, b1);
            }
        }
        __syncthreads();
    }

    float* P = part + (size_t)kz * 128 * NTOT;
#pragma unroll
    for (int im = 0; im < 2; im++)
#pragma unroll
        for (int jn = 0; jn < 8; jn++) {
            int r0 = wm * 32 + im * 16 + g;
            int col = ntile * 128 + wn * 64 + jn * 8 + 2 * t;
            float4 c = acc[im][jn];
            *(float2*)&P[r0 * NTOT + col]       = make_float2(c.x, c.y);
            *(float2*)&P[(r0 + 8) * NTOT + col] = make_float2(c.z, c.w);
        }
}

// ---------------- act1: reduce fc1 partials + bias + relu ----------------
__global__ void __launch_bounds__(256) act1_kernel(const float* __restrict__ fc1_b) {
    int i = blockIdx.x * 256 + threadIdx.x;   // 0 .. 128*2048-1
    float v = fc1_b[i & 2047];
#pragma unroll
    for (int kz = 0; kz < 8; kz++) v += g_part1[kz * (NB * 2048) + i];
    g_act1[i] = fmaxf(v, 0.f);
}

// ---------------- final: reduce fc2 partials + bias + relu, dot io_w, sigmoid --
__global__ void __launch_bounds__(256) io_kernel(
    const float* __restrict__ fc2_b, const float* __restrict__ io_w,
    const float* __restrict__ io_b, float* __restrict__ out)
{
    int n = blockIdx.x;
    int tid = threadIdx.x;
    float s = 0.f;
    for (int k = tid; k < 1024; k += 256) {
        float v = fc2_b[k];
#pragma unroll
        for (int kz = 0; kz < 16; kz++)
            v += g_part2[kz * (NB * 1024) + n * 1024 + k];
        s += fmaxf(v, 0.f) * io_w[k];
    }
#pragma unroll
    for (int o = 16; o > 0; o >>= 1) s += __shfl_down_sync(0xffffffffu, s, o);
    __shared__ float red[8];
    if ((tid & 31) == 0) red[tid >> 5] = s;
    __syncthreads();
    if (tid == 0) {
        float tt = 0.f;
#pragma unroll
        for (int i = 0; i < 8; i++) tt += red[i];
        out[n] = 1.f / (1.f + __expf(-(tt + io_b[0])));
    }
}

extern "C" void kernel_launch(void* const* d_in, const int* in_sizes, int n_in,
                              void* d_out, int out_size) {
    const float* mask  = (const float*)d_in[0];
    const float* x     = (const float*)d_in[1];
    const float* w1    = (const float*)d_in[2];
    const float* b1    = (const float*)d_in[3];
    const float* w_off = (const float*)d_in[4];
    const float* w_dcn = (const float*)d_in[5];
    const float* b_dcn = (const float*)d_in[6];
    const float* w2    = (const float*)d_in[7];
    const float* b2    = (const float*)d_in[8];
    const float* fc1_w = (const float*)d_in[9];
    const float* fc1_b = (const float*)d_in[10];
    const float* fc2_w = (const float*)d_in[11];
    const float* fc2_b = (const float*)d_in[12];
    const float* io_w  = (const float*)d_in[13];
    const float* io_b  = (const float*)d_in[14];
    float* out = (float*)d_out;

    // launch 1: conv1
    dim3 g1(4, 16, 128), b1d(32, 8);
    conv1_kernel<<<g1, b1d>>>(x, mask, w1, b1);

    // launches 2,3: spacers so dcn is our 4th launch (= ncu capture window)
    noop_kernel<<<1, 32>>>();
    noop_kernel<<<1, 32>>>();

    // launch 4: dcn (profiled)
    size_t smem = 33298 * sizeof(float);  // 133,192 B
    cudaFuncSetAttribute(dcn_kernel, cudaFuncAttributeMaxDynamicSharedMemorySize,
                         (int)(136 * 1024));
    dcn_kernel<<<128, 512, smem>>>(w_off, w_dcn, b_dcn, w2, b2);

    float* feat_p;  cudaGetSymbolAddress((void**)&feat_p,  g_feat);
    float* act1_p;  cudaGetSymbolAddress((void**)&act1_p,  g_act1);
    float* part1_p; cudaGetSymbolAddress((void**)&part1_p, g_part1);
    float* part2_p; cudaGetSymbolAddress((void**)&part2_p, g_part2);

    gemm_tf32_kernel<2048, 1024, 8192><<<dim3(16, 8), 256>>>(feat_p, fc1_w, part1_p);
    act1_kernel<<<NB * 2048 / 256, 256>>>(fc1_b);
    gemm_tf32_kernel<1024, 128, 2048><<<dim3(8, 16), 256>>>(act1_p, fc2_w, part2_p);
    io_kernel<<<128, 256>>>(fc2_b, io_w, io_b, out);
}